// round 1
// baseline (speedup 1.0000x reference)
#include <cuda_runtime.h>

// Problem constants
#define NN    2048
#define HALF  1024
#define F     128     // IN_C == HID == 128
#define LATD  64
#define ES    65536

// ---------------- scratch (device globals; no runtime alloc) ----------------
__device__ float g_ST[HALF * HALF];   // S^T : ST[c*1024 + r] = sigmoid(my[r,c])
__device__ float g_deg[NN];
__device__ float g_dinv[NN];
__device__ int   g_cnt[NN];
__device__ int   g_ptr[NN + 1];
__device__ int   g_cur[NN];
__device__ int   g_csrc[ES];
__device__ float g_hs[NN * F];        // dinv-scaled features (aggregation input)
__device__ float g_acc[NN * F];       // aggregation accumulator / agg2 output

// ---------------- init: deg = 1 (self loop), cnt = 0 ----------------
__global__ void k_init() {
    int i = blockIdx.x * blockDim.x + threadIdx.x;
    if (i < NN) { g_deg[i] = 1.0f; g_cnt[i] = 0; }
}

// ---------------- sigmoid + transpose + column-sum of the dense block -------
// masked_y is [2048,2048]; use top-left [1024,1024].
__global__ void k_sig_tr(const float* __restrict__ my) {
    __shared__ float sm[32][33];
    int c = blockIdx.x * 32 + threadIdx.x;
    int r = blockIdx.y * 32 + threadIdx.y;
    float v = 1.0f / (1.0f + __expf(-my[r * 2048 + c]));
    sm[threadIdx.y][threadIdx.x] = v;
    __syncthreads();
    // transposed write: ST[(c0+ty)][r0+tx]
    int co = blockIdx.x * 32 + threadIdx.y;
    int ro = blockIdx.y * 32 + threadIdx.x;
    g_ST[co * HALF + ro] = sm[threadIdx.x][threadIdx.y];
    __syncthreads();
    // column sum over the 32 rows of this tile (reduce along ty)
    for (int s = 16; s > 0; s >>= 1) {
        if (threadIdx.y < s) sm[threadIdx.y][threadIdx.x] += sm[threadIdx.y + s][threadIdx.x];
        __syncthreads();
    }
    if (threadIdx.y == 0) atomicAdd(&g_deg[c], sm[0][threadIdx.x]);
}

// ---------------- sparse edges: degree + bucket histogram ----------------
__global__ void k_sparse_deg(const int* __restrict__ ei) {
    int e = blockIdx.x * blockDim.x + threadIdx.x;
    if (e < ES) {
        int dst = ei[ES + e];
        atomicAdd(&g_deg[dst], 1.0f);
        atomicAdd(&g_cnt[dst], 1);
    }
}

// ---------------- scan (CSR ptr) + dinv ----------------
__global__ void k_scan() {
    __shared__ int ss[1024];
    int t = threadIdx.x;
    int a = g_cnt[2 * t], b = g_cnt[2 * t + 1];
    int s = a + b;
    ss[t] = s;
    __syncthreads();
    for (int off = 1; off < 1024; off <<= 1) {
        int v = (t >= off) ? ss[t - off] : 0;
        __syncthreads();
        ss[t] += v;
        __syncthreads();
    }
    int excl = ss[t] - s;
    g_ptr[2 * t] = excl;     g_ptr[2 * t + 1] = excl + a;
    g_cur[2 * t] = excl;     g_cur[2 * t + 1] = excl + a;
    if (t == 1023) g_ptr[NN] = ss[t];
    g_dinv[2 * t]     = rsqrtf(g_deg[2 * t]);       // deg >= 1 always (self loop)
    g_dinv[2 * t + 1] = rsqrtf(g_deg[2 * t + 1]);
}

// ---------------- CSR fill ----------------
__global__ void k_fill(const int* __restrict__ ei) {
    int e = blockIdx.x * blockDim.x + threadIdx.x;
    if (e < ES) {
        int dst = ei[ES + e];
        int pos = atomicAdd(&g_cur[dst], 1);
        g_csrc[pos] = ei[e];
    }
}

// ---------------- generic tiled fp32 GEMM: C = op(A@B) -------------------
// BM=64, BN=64, BK=16, 256 threads, 4x4 micro-tile. M,N multiples of 64, K of 16.
template <bool RSCALE, bool BIAS>
__global__ void k_gemm(const float* __restrict__ A, const float* __restrict__ B,
                       float* __restrict__ C, int M, int Nc, int Kc,
                       const float* __restrict__ rs, const float* __restrict__ bias) {
    __shared__ float As[16][65];
    __shared__ float Bs[16][65];
    int col0 = blockIdx.x * 64;
    int row0 = blockIdx.y * 64;
    int tid = threadIdx.x;
    int tx = tid % 16, ty = tid / 16;
    float acc[4][4] = {};
    for (int k0 = 0; k0 < Kc; k0 += 16) {
        for (int l = tid; l < 64 * 16; l += 256) {
            int i = l / 16, kk = l % 16;
            As[kk][i] = A[(row0 + i) * Kc + k0 + kk];
        }
        for (int l = tid; l < 16 * 64; l += 256) {
            int kk = l / 64, j = l % 64;
            Bs[kk][j] = B[(k0 + kk) * Nc + col0 + j];
        }
        __syncthreads();
#pragma unroll
        for (int kk = 0; kk < 16; kk++) {
            float a[4], b[4];
#pragma unroll
            for (int m = 0; m < 4; m++) a[m] = As[kk][ty + m * 16];
#pragma unroll
            for (int n = 0; n < 4; n++) b[n] = Bs[kk][tx + n * 16];
#pragma unroll
            for (int m = 0; m < 4; m++)
#pragma unroll
                for (int n = 0; n < 4; n++) acc[m][n] += a[m] * b[n];
        }
        __syncthreads();
    }
#pragma unroll
    for (int m = 0; m < 4; m++) {
        int r = row0 + ty + m * 16;
        float sc = RSCALE ? rs[r] : 1.0f;
#pragma unroll
        for (int n = 0; n < 4; n++) {
            int c = col0 + tx + n * 16;
            float v = acc[m][n];
            if (RSCALE) v *= sc;
            if (BIAS)   v += bias[c];
            C[r * Nc + c] = v;
        }
    }
}

// ---------------- sparse + self-loop aggregation (CSR gather) ----------------
// acc[c,:] = in[c,:] + sum_{e in bucket(c)} in[src_e,:]
__global__ void k_agg_edge(const float* __restrict__ in) {
    int c = blockIdx.x;
    int f = threadIdx.x;
    float acc = in[c * F + f];     // self loop
    int p = g_ptr[c], p1 = g_ptr[c + 1];
    for (; p + 4 <= p1; p += 4) {
        int s0 = g_csrc[p], s1 = g_csrc[p + 1], s2 = g_csrc[p + 2], s3 = g_csrc[p + 3];
        acc += in[s0 * F + f];
        acc += in[s1 * F + f];
        acc += in[s2 * F + f];
        acc += in[s3 * F + f];
    }
    for (; p < p1; ++p) acc += in[g_csrc[p] * F + f];
    g_acc[c * F + f] = acc;
}

// ---------------- dense-block aggregation: acc[c,:] += ST[c,:] @ in[:1024,:] -
// BM=64 (c), BN=128 (f), split-K (KSPLIT=8, slice=128), atomicAdd epilogue.
#define KSPLIT 8
__global__ void k_agg_dense(const float* __restrict__ in) {
    __shared__ float As[16][65];    // As[k][i], i<64
    __shared__ float Bs[16][128];
    int c0 = blockIdx.x * 64;
    int kbase = blockIdx.z * (HALF / KSPLIT);
    int tid = threadIdx.x;
    int tx = tid % 16, ty = tid / 16;
    float acc[4][8] = {};
    for (int k0 = kbase; k0 < kbase + HALF / KSPLIT; k0 += 16) {
        for (int l = tid; l < 64 * 16; l += 256) {
            int i = l / 16, kk = l % 16;
            As[kk][i] = g_ST[(c0 + i) * HALF + k0 + kk];
        }
        for (int l = tid; l < 16 * 128; l += 256) {
            int kk = l / 128, f = l % 128;
            Bs[kk][f] = in[(k0 + kk) * F + f];
        }
        __syncthreads();
#pragma unroll
        for (int kk = 0; kk < 16; kk++) {
            float a[4], b[8];
#pragma unroll
            for (int m = 0; m < 4; m++) a[m] = As[kk][ty + m * 16];
#pragma unroll
            for (int n = 0; n < 8; n++) b[n] = Bs[kk][tx + n * 16];
#pragma unroll
            for (int m = 0; m < 4; m++)
#pragma unroll
                for (int n = 0; n < 8; n++) acc[m][n] += a[m] * b[n];
        }
        __syncthreads();
    }
#pragma unroll
    for (int m = 0; m < 4; m++)
#pragma unroll
        for (int n = 0; n < 8; n++)
            atomicAdd(&g_acc[(c0 + ty + m * 16) * F + tx + n * 16], acc[m][n]);
}

// ---------------- epilogues ----------------
// stage1: hs <- dinv * relu(dinv*acc + b1)
__global__ void k_fin1(const float* __restrict__ b1) {
    int idx = blockIdx.x * blockDim.x + threadIdx.x;
    if (idx < NN * F) {
        int row = idx >> 7, col = idx & 127;
        float d = g_dinv[row];
        float h = fmaxf(d * g_acc[idx] + b1[col], 0.0f);
        g_hs[idx] = d * h;
    }
}
// stage2: acc <- dinv * acc   (bias folded into final GEMMs)
__global__ void k_fin2() {
    int idx = blockIdx.x * blockDim.x + threadIdx.x;
    if (idx < NN * F) g_acc[idx] *= g_dinv[idx >> 7];
}

// ---------------- launch ----------------
extern "C" void kernel_launch(void* const* d_in, const int* in_sizes, int n_in,
                              void* d_out, int out_size) {
    const float* x   = (const float*)d_in[0];
    const float* my  = (const float*)d_in[1];
    const float* W1  = (const float*)d_in[2];
    const float* b1  = (const float*)d_in[3];
    const float* Wmu = (const float*)d_in[4];
    const float* bmu = (const float*)d_in[5];
    const float* Wls = (const float*)d_in[6];
    const float* bls = (const float*)d_in[7];
    const int*   ei  = (const int*)d_in[8];
    float* out = (float*)d_out;

    float* d_hs;   cudaGetSymbolAddress((void**)&d_hs,  g_hs);
    float* d_acc;  cudaGetSymbolAddress((void**)&d_acc, g_acc);
    float* d_dinv; cudaGetSymbolAddress((void**)&d_dinv, g_dinv);

    // graph preprocessing
    k_init<<<(NN + 255) / 256, 256>>>();
    k_sig_tr<<<dim3(HALF / 32, HALF / 32), dim3(32, 32)>>>(my);
    k_sparse_deg<<<ES / 256, 256>>>(ei);
    k_scan<<<1, 1024>>>();
    k_fill<<<ES / 256, 256>>>(ei);

    // layer 1: hs = dinv * (x @ W1)
    k_gemm<true, false><<<dim3(128 / 64, 2048 / 64), 256>>>(x, W1, d_hs, NN, F, F, d_dinv, nullptr);
    // aggregate
    k_agg_edge<<<NN, F>>>(d_hs);
    k_agg_dense<<<dim3(HALF / 64, 1, KSPLIT), 256>>>(d_hs);
    k_fin1<<<(NN * F + 255) / 256, 256>>>(b1);

    // layer 2 aggregation on hidden (128-wide, shared by mu & logstd)
    k_agg_edge<<<NN, F>>>(d_hs);
    k_agg_dense<<<dim3(HALF / 64, 1, KSPLIT), 256>>>(d_hs);
    k_fin2<<<(NN * F + 255) / 256, 256>>>();

    // z_mu = agg2 @ Wmu + bmu ; z_logstd = agg2 @ Wls + bls
    k_gemm<false, true><<<dim3(1, 2048 / 64), 256>>>(d_acc, Wmu, out,                NN, LATD, F, nullptr, bmu);
    k_gemm<false, true><<<dim3(1, 2048 / 64), 256>>>(d_acc, Wls, out + NN * LATD,    NN, LATD, F, nullptr, bls);
}

// round 2
// speedup vs baseline: 1.2769x; 1.2769x over previous
#include <cuda_runtime.h>

#define NN    2048
#define HALF  1024
#define F     128
#define LATD  64
#define ES    65536

// ---------------- scratch (device globals) ----------------
__device__ float g_S[HALF * HALF];    // sigmoid(my[r,c]) at [r*1024 + c]
__device__ float g_colsum[HALF];
__device__ float g_dinv[NN];
__device__ int   g_cnt[NN];
__device__ int   g_ptr[NN + 1];
__device__ int   g_cur[NN];
__device__ int   g_csrc[ES];
__device__ float g_h[NN * F];         // raw x@W1
__device__ float g_hsd[NN * F];       // dinv-scaled aggregation input
__device__ float g_acc[NN * F];       // aggregation accumulator

// ---------------- packed f32x2 helpers (SASS FFMA2) ----------------
__device__ __forceinline__ unsigned long long pk2(float lo, float hi) {
    unsigned long long r;
    asm("mov.b64 %0, {%1, %2};" : "=l"(r) : "f"(lo), "f"(hi));
    return r;
}
__device__ __forceinline__ float2 upk2(unsigned long long v) {
    float2 f;
    asm("mov.b64 {%0, %1}, %2;" : "=f"(f.x), "=f"(f.y) : "l"(v));
    return f;
}
__device__ __forceinline__ void fma2(unsigned long long& c,
                                     unsigned long long a, unsigned long long b) {
    asm("fma.rn.f32x2 %0, %1, %2, %3;" : "=l"(c) : "l"(a), "l"(b), "l"(c));
}

// ================= mega kernel A: sigmoid+colsum | sparse count | gemm1 ======
// blocks [0,1024): sigmoid tile 32x32 + column sums
// blocks [1024,1280): sparse dst counting
// blocks [1280,1344): g_h = x @ W1  (2048x128x128), BM=64 BN=64 BK=16
__global__ void k_megaA(const float* __restrict__ my, const int* __restrict__ ei,
                        const float* __restrict__ x, const float* __restrict__ W1) {
    int b = blockIdx.x;
    int tid = threadIdx.x;
    if (b < 1024) {
        __shared__ float sm[256];
        int r0 = (b >> 5) * 32, c0 = (b & 31) * 32;
        int tx = tid & 31, ty = tid >> 5;
        int c = c0 + tx;
        float csum = 0.f;
#pragma unroll
        for (int rr = 0; rr < 4; rr++) {
            int r = r0 + ty + rr * 8;
            float v = 1.0f / (1.0f + __expf(-my[r * 2048 + c]));
            g_S[r * HALF + c] = v;
            csum += v;
        }
        sm[tid] = csum;
        __syncthreads();
        if (ty < 4) sm[tid] += sm[tid + 128];
        __syncthreads();
        if (ty < 2) sm[tid] += sm[tid + 64];
        __syncthreads();
        if (ty == 0) atomicAdd(&g_colsum[c], sm[tid] + sm[tid + 32]);
    } else if (b < 1280) {
        int e = (b - 1024) * 256 + tid;
        atomicAdd(&g_cnt[ei[ES + e]], 1);
    } else {
        __shared__ float As[16][65];
        __shared__ float Bs[16 * 64];
        int bid = b - 1280;
        int col0 = (bid & 1) * 64;
        int row0 = (bid >> 1) * 64;
        int tx = tid & 15, ty = tid >> 4;
        unsigned long long acc[4][2] = {};
        for (int k0 = 0; k0 < 128; k0 += 16) {
            for (int l = tid; l < 64 * 16; l += 256) {
                int i = l >> 4, kk = l & 15;
                As[kk][i] = x[(row0 + i) * 128 + k0 + kk];
            }
            for (int l = tid; l < 16 * 64; l += 256) {
                int kk = l >> 6, j = l & 63;
                Bs[kk * 64 + j] = W1[(k0 + kk) * 128 + col0 + j];
            }
            __syncthreads();
#pragma unroll
            for (int kk = 0; kk < 16; kk++) {
                unsigned long long ad[4], bb[2];
#pragma unroll
                for (int m = 0; m < 4; m++) { float a = As[kk][ty + m * 16]; ad[m] = pk2(a, a); }
                const float2* brow = (const float2*)(Bs + kk * 64);
#pragma unroll
                for (int n = 0; n < 2; n++) { float2 bv = brow[tx + n * 16]; bb[n] = pk2(bv.x, bv.y); }
#pragma unroll
                for (int m = 0; m < 4; m++)
#pragma unroll
                    for (int n = 0; n < 2; n++) fma2(acc[m][n], ad[m], bb[n]);
            }
            __syncthreads();
        }
#pragma unroll
        for (int m = 0; m < 4; m++) {
            int r = row0 + ty + m * 16;
#pragma unroll
            for (int n = 0; n < 2; n++) {
                float2 v = upk2(acc[m][n]);
                int cc = col0 + 2 * (tx + n * 16);
                g_h[r * 128 + cc] = v.x;
                g_h[r * 128 + cc + 1] = v.y;
            }
        }
    }
}

// ================= scan: CSR ptr + dinv (shuffle-based, 2 barriers) =========
__global__ void k_scan() {
    int t = threadIdx.x;
    int a = g_cnt[2 * t], b2 = g_cnt[2 * t + 1];
    int s = a + b2;
    int lane = t & 31, w = t >> 5;
    int v = s;
#pragma unroll
    for (int off = 1; off < 32; off <<= 1) {
        int u = __shfl_up_sync(0xffffffffu, v, off);
        if (lane >= off) v += u;
    }
    __shared__ int wsum[32];
    if (lane == 31) wsum[w] = v;
    __syncthreads();
    if (w == 0) {
        int xx = wsum[lane];
#pragma unroll
        for (int off = 1; off < 32; off <<= 1) {
            int u = __shfl_up_sync(0xffffffffu, xx, off);
            if (lane >= off) xx += u;
        }
        wsum[lane] = xx;
    }
    __syncthreads();
    int base = (w > 0) ? wsum[w - 1] : 0;
    int excl = base + v - s;
    g_ptr[2 * t] = excl;       g_ptr[2 * t + 1] = excl + a;
    g_cur[2 * t] = excl;       g_cur[2 * t + 1] = excl + a;
    if (t == 1023) g_ptr[NN] = ES;
    float d0 = 1.0f + (float)a  + (2 * t     < HALF ? g_colsum[2 * t]     : 0.f);
    float d1 = 1.0f + (float)b2 + (2 * t + 1 < HALF ? g_colsum[2 * t + 1] : 0.f);
    g_dinv[2 * t]     = rsqrtf(d0);
    g_dinv[2 * t + 1] = rsqrtf(d1);
}

// ================= CSR fill | hsd = dinv * h =================================
__global__ void k_fill_scale(const int* __restrict__ ei) {
    int b = blockIdx.x, tid = threadIdx.x;
    if (b < 256) {
        int e = b * 256 + tid;
        int dst = ei[ES + e];
        int pos = atomicAdd(&g_cur[dst], 1);
        g_csrc[pos] = ei[e];
    } else {
        int idx = (b - 256) * 256 + tid;
        g_hsd[idx] = g_h[idx] * g_dinv[idx >> 7];
    }
}

// ================= aggregation: dense GEMM part | edge CSR part ==============
// in = pre-scaled (dinv[src]*h[src]).  g_acc must be zeroed beforehand.
// blocks [0,128): acc[c,:] += S^T-slice @ in  (BM=64, full N=128, K-slice=128)
// blocks [128,1152): acc[c,:] += in[c,:] + sum_edges in[src,:]
__global__ void k_agg(const float* __restrict__ in) {
    int b = blockIdx.x, tid = threadIdx.x;
    if (b < 128) {
        __shared__ float As[16][65];
        __shared__ float Bs[16 * 128];
        int c0 = (b & 15) * 64;
        int kbase = (b >> 4) * 128;
        int tx = tid & 15, ty = tid >> 4;
        unsigned long long acc[4][4] = {};
        for (int k0 = kbase; k0 < kbase + 128; k0 += 16) {
            for (int l = tid; l < 64 * 16; l += 256) {
                int kk = l >> 6, i = l & 63;
                As[kk][i] = g_S[(k0 + kk) * HALF + c0 + i];
            }
            for (int l = tid; l < 16 * 128; l += 256) {
                int kk = l >> 7, f = l & 127;
                Bs[kk * 128 + f] = in[(k0 + kk) * F + f];
            }
            __syncthreads();
#pragma unroll
            for (int kk = 0; kk < 16; kk++) {
                unsigned long long ad[4], bb[4];
#pragma unroll
                for (int m = 0; m < 4; m++) { float a = As[kk][ty + m * 16]; ad[m] = pk2(a, a); }
                const float2* brow = (const float2*)(Bs + kk * 128);
#pragma unroll
                for (int n = 0; n < 4; n++) { float2 bv = brow[tx + n * 16]; bb[n] = pk2(bv.x, bv.y); }
#pragma unroll
                for (int m = 0; m < 4; m++)
#pragma unroll
                    for (int n = 0; n < 4; n++) fma2(acc[m][n], ad[m], bb[n]);
            }
            __syncthreads();
        }
#pragma unroll
        for (int m = 0; m < 4; m++) {
            int c = c0 + ty + m * 16;
#pragma unroll
            for (int n = 0; n < 4; n++) {
                float2 v = upk2(acc[m][n]);
                int f = 2 * (tx + n * 16);
                atomicAdd(&g_acc[c * F + f],     v.x);
                atomicAdd(&g_acc[c * F + f + 1], v.y);
            }
        }
    } else {
        int c = (b - 128) * 2 + (tid >> 7);
        int f = tid & 127;
        float acc = in[c * F + f];   // self loop (pre-scaled by dinv[c])
        int p = g_ptr[c], p1 = g_ptr[c + 1];
        for (; p + 4 <= p1; p += 4) {
            int s0 = g_csrc[p], s1 = g_csrc[p + 1], s2 = g_csrc[p + 2], s3 = g_csrc[p + 3];
            acc += in[s0 * F + f] + in[s1 * F + f] + in[s2 * F + f] + in[s3 * F + f];
        }
        for (; p < p1; p++) acc += in[g_csrc[p] * F + f];
        atomicAdd(&g_acc[c * F + f], acc);
    }
}

// ================= fin1: hsd = dinv*relu(dinv*acc + b1); acc = 0 =============
__global__ void k_fin1(const float* __restrict__ b1) {
    int idx = blockIdx.x * 256 + threadIdx.x;
    int r = idx >> 7;
    float d = g_dinv[r];
    float h = fmaxf(d * g_acc[idx] + b1[idx & 127], 0.f);
    g_hsd[idx] = d * h;
    g_acc[idx] = 0.f;
}

// ================= output: z = (dinv*acc) @ W + bias  (z selects mu/ls) ======
__global__ void k_out(const float* __restrict__ Wmu, const float* __restrict__ bmu,
                      const float* __restrict__ Wls, const float* __restrict__ bls,
                      float* __restrict__ out) {
    __shared__ float As[16][65];
    __shared__ float Bs[16 * 64];
    int z = blockIdx.y;
    const float* W    = z ? Wls : Wmu;
    const float* bias = z ? bls : bmu;
    float* C = out + z * NN * LATD;
    int row0 = blockIdx.x * 64;
    int tid = threadIdx.x;
    int tx = tid & 15, ty = tid >> 4;
    unsigned long long acc[4][2] = {};
    for (int k0 = 0; k0 < 128; k0 += 16) {
        for (int l = tid; l < 64 * 16; l += 256) {
            int i = l >> 4, kk = l & 15;
            As[kk][i] = g_acc[(row0 + i) * F + k0 + kk] * g_dinv[row0 + i];
        }
        for (int l = tid; l < 16 * 64; l += 256) {
            int kk = l >> 6, j = l & 63;
            Bs[kk * 64 + j] = W[(k0 + kk) * LATD + j];
        }
        __syncthreads();
#pragma unroll
        for (int kk = 0; kk < 16; kk++) {
            unsigned long long ad[4], bb[2];
#pragma unroll
            for (int m = 0; m < 4; m++) { float a = As[kk][ty + m * 16]; ad[m] = pk2(a, a); }
            const float2* brow = (const float2*)(Bs + kk * 64);
#pragma unroll
            for (int n = 0; n < 2; n++) { float2 bv = brow[tx + n * 16]; bb[n] = pk2(bv.x, bv.y); }
#pragma unroll
            for (int m = 0; m < 4; m++)
#pragma unroll
                for (int n = 0; n < 2; n++) fma2(acc[m][n], ad[m], bb[n]);
        }
        __syncthreads();
    }
#pragma unroll
    for (int m = 0; m < 4; m++) {
        int r = row0 + ty + m * 16;
#pragma unroll
        for (int n = 0; n < 2; n++) {
            float2 v = upk2(acc[m][n]);
            int cc = 2 * (tx + n * 16);
            C[r * LATD + cc]     = v.x + bias[cc];
            C[r * LATD + cc + 1] = v.y + bias[cc + 1];
        }
    }
}

// ================= launch ====================================================
extern "C" void kernel_launch(void* const* d_in, const int* in_sizes, int n_in,
                              void* d_out, int out_size) {
    const float* x   = (const float*)d_in[0];
    const float* my  = (const float*)d_in[1];
    const float* W1  = (const float*)d_in[2];
    const float* b1  = (const float*)d_in[3];
    const float* Wmu = (const float*)d_in[4];
    const float* bmu = (const float*)d_in[5];
    const float* Wls = (const float*)d_in[6];
    const float* bls = (const float*)d_in[7];
    const int*   ei  = (const int*)d_in[8];
    float* out = (float*)d_out;

    void *p_colsum, *p_cnt, *p_acc, *p_hsd;
    cudaGetSymbolAddress(&p_colsum, g_colsum);
    cudaGetSymbolAddress(&p_cnt,    g_cnt);
    cudaGetSymbolAddress(&p_acc,    g_acc);
    cudaGetSymbolAddress(&p_hsd,    g_hsd);

    cudaMemsetAsync(p_colsum, 0, HALF * sizeof(float));
    cudaMemsetAsync(p_cnt,    0, NN * sizeof(int));
    cudaMemsetAsync(p_acc,    0, NN * F * sizeof(float));

    k_megaA<<<1344, 256>>>(my, ei, x, W1);
    k_scan<<<1, 1024>>>();
    k_fill_scale<<<1280, 256>>>(ei);

    k_agg<<<1152, 256>>>((const float*)p_hsd);
    k_fin1<<<1024, 256>>>(b1);
    k_agg<<<1152, 256>>>((const float*)p_hsd);

    k_out<<<dim3(32, 2), 256>>>(Wmu, bmu, Wls, bls, out);
}

// round 3
// speedup vs baseline: 1.3666x; 1.0703x over previous
#include <cuda_runtime.h>

#define NN    2048
#define HALF  1024
#define F     128
#define LATD  64
#define ES    65536

// ---------------- scratch (device globals) ----------------
__device__ float g_S[HALF * HALF];    // sigmoid(my[r,c]) at [r*1024 + c]
__device__ float g_colsum[HALF];
__device__ float g_dinv[NN];
__device__ int   g_cnt[NN];
__device__ int   g_ptr[NN + 1];
__device__ int   g_cur[NN];
__device__ int   g_csrc[ES];
__device__ float g_h[NN * F];         // raw x@W1
__device__ float g_hsd[NN * F];       // dinv-scaled aggregation input
__device__ float g_acc[NN * F];       // aggregation accumulator

// ---------------- packed f32x2 helpers (SASS FFMA2) ----------------
__device__ __forceinline__ unsigned long long pk2(float lo, float hi) {
    unsigned long long r;
    asm("mov.b64 %0, {%1, %2};" : "=l"(r) : "f"(lo), "f"(hi));
    return r;
}
__device__ __forceinline__ float2 upk2(unsigned long long v) {
    float2 f;
    asm("mov.b64 {%0, %1}, %2;" : "=f"(f.x), "=f"(f.y) : "l"(v));
    return f;
}
__device__ __forceinline__ void fma2(unsigned long long& c,
                                     unsigned long long a, unsigned long long b) {
    asm("fma.rn.f32x2 %0, %1, %2, %3;" : "=l"(c) : "l"(a), "l"(b), "l"(c));
}

// ================= mega kernel A: sigmoid+colsum | sparse count | gemm1 ======
__global__ void k_megaA(const float* __restrict__ my, const int* __restrict__ ei,
                        const float* __restrict__ x, const float* __restrict__ W1) {
    int b = blockIdx.x;
    int tid = threadIdx.x;
    if (b < 1024) {
        __shared__ float sm[256];
        int r0 = (b >> 5) * 32, c0 = (b & 31) * 32;
        int tx = tid & 31, ty = tid >> 5;
        int c = c0 + tx;
        float csum = 0.f;
#pragma unroll
        for (int rr = 0; rr < 4; rr++) {
            int r = r0 + ty + rr * 8;
            float v = 1.0f / (1.0f + __expf(-my[r * 2048 + c]));
            g_S[r * HALF + c] = v;
            csum += v;
        }
        sm[tid] = csum;
        __syncthreads();
        if (ty < 4) sm[tid] += sm[tid + 128];
        __syncthreads();
        if (ty < 2) sm[tid] += sm[tid + 64];
        __syncthreads();
        if (ty == 0) atomicAdd(&g_colsum[c], sm[tid] + sm[tid + 32]);
    } else if (b < 1280) {
        int e = (b - 1024) * 256 + tid;
        atomicAdd(&g_cnt[ei[ES + e]], 1);
    } else {
        __shared__ float As[16][65];
        __shared__ float Bs[16 * 64];
        int bid = b - 1280;
        int col0 = (bid & 1) * 64;
        int row0 = (bid >> 1) * 64;
        int tx = tid & 15, ty = tid >> 4;
        unsigned long long acc[4][2] = {};
        for (int k0 = 0; k0 < 128; k0 += 16) {
            for (int l = tid; l < 64 * 16; l += 256) {
                int i = l >> 4, kk = l & 15;
                As[kk][i] = x[(row0 + i) * 128 + k0 + kk];
            }
            for (int l = tid; l < 16 * 64; l += 256) {
                int kk = l >> 6, j = l & 63;
                Bs[kk * 64 + j] = W1[(k0 + kk) * 128 + col0 + j];
            }
            __syncthreads();
#pragma unroll
            for (int kk = 0; kk < 16; kk++) {
                unsigned long long ad[4], bb[2];
#pragma unroll
                for (int m = 0; m < 4; m++) { float a = As[kk][ty + m * 16]; ad[m] = pk2(a, a); }
                const float2* brow = (const float2*)(Bs + kk * 64);
#pragma unroll
                for (int n = 0; n < 2; n++) { float2 bv = brow[tx + n * 16]; bb[n] = pk2(bv.x, bv.y); }
#pragma unroll
                for (int m = 0; m < 4; m++)
#pragma unroll
                    for (int n = 0; n < 2; n++) fma2(acc[m][n], ad[m], bb[n]);
            }
            __syncthreads();
        }
#pragma unroll
        for (int m = 0; m < 4; m++) {
            int r = row0 + ty + m * 16;
#pragma unroll
            for (int n = 0; n < 2; n++) {
                float2 v = upk2(acc[m][n]);
                int cc = col0 + 2 * (tx + n * 16);
                g_h[r * 128 + cc] = v.x;
                g_h[r * 128 + cc + 1] = v.y;
            }
        }
    }
}

// ================= scan: CSR ptr + dinv (shuffle-based) ======================
__global__ void k_scan() {
    int t = threadIdx.x;
    int a = g_cnt[2 * t], b2 = g_cnt[2 * t + 1];
    int s = a + b2;
    int lane = t & 31, w = t >> 5;
    int v = s;
#pragma unroll
    for (int off = 1; off < 32; off <<= 1) {
        int u = __shfl_up_sync(0xffffffffu, v, off);
        if (lane >= off) v += u;
    }
    __shared__ int wsum[32];
    if (lane == 31) wsum[w] = v;
    __syncthreads();
    if (w == 0) {
        int xx = wsum[lane];
#pragma unroll
        for (int off = 1; off < 32; off <<= 1) {
            int u = __shfl_up_sync(0xffffffffu, xx, off);
            if (lane >= off) xx += u;
        }
        wsum[lane] = xx;
    }
    __syncthreads();
    int base = (w > 0) ? wsum[w - 1] : 0;
    int excl = base + v - s;
    g_ptr[2 * t] = excl;       g_ptr[2 * t + 1] = excl + a;
    g_cur[2 * t] = excl;       g_cur[2 * t + 1] = excl + a;
    if (t == 1023) g_ptr[NN] = ES;
    float d0 = 1.0f + (float)a  + (2 * t     < HALF ? g_colsum[2 * t]     : 0.f);
    float d1 = 1.0f + (float)b2 + (2 * t + 1 < HALF ? g_colsum[2 * t + 1] : 0.f);
    g_dinv[2 * t]     = rsqrtf(d0);
    g_dinv[2 * t + 1] = rsqrtf(d1);
}

// ================= CSR fill | hsd = dinv * h (float4) ========================
__global__ void k_fill_scale(const int* __restrict__ ei) {
    int b = blockIdx.x, tid = threadIdx.x;
    if (b < 256) {
        int e = b * 256 + tid;
        int dst = ei[ES + e];
        int pos = atomicAdd(&g_cur[dst], 1);
        g_csrc[pos] = ei[e];
    } else {
        int idx = (b - 256) * 256 + tid;            // float4 index, 65536 total
        float d = g_dinv[idx >> 5];
        float4 a = ((const float4*)g_h)[idx];
        a.x *= d; a.y *= d; a.z *= d; a.w *= d;
        ((float4*)g_hsd)[idx] = a;
    }
}

// ================= edge + self-loop aggregation (plain store, runs FIRST) ====
// acc[c,:] = in[c,:] + sum_{e in bucket(c)} in[src_e,:]
__global__ void __launch_bounds__(128, 12) k_agg_edge(const float* __restrict__ in) {
    int c = blockIdx.x;
    int f = threadIdx.x;
    float acc = in[c * F + f];                      // self loop (pre-scaled)
    int p = g_ptr[c], p1 = g_ptr[c + 1];
    for (; p + 8 <= p1; p += 8) {
        int s0 = g_csrc[p],     s1 = g_csrc[p + 1], s2 = g_csrc[p + 2], s3 = g_csrc[p + 3];
        int s4 = g_csrc[p + 4], s5 = g_csrc[p + 5], s6 = g_csrc[p + 6], s7 = g_csrc[p + 7];
        float a0 = in[s0 * F + f] + in[s1 * F + f];
        float a1 = in[s2 * F + f] + in[s3 * F + f];
        float a2 = in[s4 * F + f] + in[s5 * F + f];
        float a3 = in[s6 * F + f] + in[s7 * F + f];
        acc += (a0 + a1) + (a2 + a3);
    }
    for (; p < p1; p++) acc += in[g_csrc[p] * F + f];
    g_acc[c * F + f] = acc;                         // plain store — initializes acc
}

// ================= dense aggregation: acc[c,:] += S^T-slice @ in =============
// 256 blocks: 16 c-tiles x KSPLIT 16 (64 k each). atomicAdd on top of edge pass.
__global__ void __launch_bounds__(256) k_agg_dense(const float* __restrict__ in) {
    __shared__ float As[16][65];
    __shared__ float Bs[16 * 128];
    int c0 = (blockIdx.x & 15) * 64;
    int kbase = (blockIdx.x >> 4) * 64;
    int tid = threadIdx.x;
    int tx = tid & 15, ty = tid >> 4;
    unsigned long long acc[4][4] = {};
    for (int k0 = kbase; k0 < kbase + 64; k0 += 16) {
        for (int l = tid; l < 64 * 16; l += 256) {
            int kk = l >> 6, i = l & 63;
            As[kk][i] = g_S[(k0 + kk) * HALF + c0 + i];
        }
        for (int l = tid; l < 16 * 128; l += 256) {
            int kk = l >> 7, f = l & 127;
            Bs[kk * 128 + f] = in[(k0 + kk) * F + f];
        }
        __syncthreads();
#pragma unroll
        for (int kk = 0; kk < 16; kk++) {
            unsigned long long ad[4], bb[4];
#pragma unroll
            for (int m = 0; m < 4; m++) { float a = As[kk][ty + m * 16]; ad[m] = pk2(a, a); }
            const float2* brow = (const float2*)(Bs + kk * 128);
#pragma unroll
            for (int n = 0; n < 4; n++) { float2 bv = brow[tx + n * 16]; bb[n] = pk2(bv.x, bv.y); }
#pragma unroll
            for (int m = 0; m < 4; m++)
#pragma unroll
                for (int n = 0; n < 4; n++) fma2(acc[m][n], ad[m], bb[n]);
        }
        __syncthreads();
    }
#pragma unroll
    for (int m = 0; m < 4; m++) {
        int c = c0 + ty + m * 16;
#pragma unroll
        for (int n = 0; n < 4; n++) {
            float2 v = upk2(acc[m][n]);
            int f = 2 * (tx + n * 16);
            atomicAdd(&g_acc[c * F + f],     v.x);
            atomicAdd(&g_acc[c * F + f + 1], v.y);
        }
    }
}

// ================= fin1: hsd = dinv*relu(dinv*acc + b1)  (float4) ============
__global__ void k_fin1(const float* __restrict__ b1) {
    int idx = blockIdx.x * 256 + threadIdx.x;       // float4 index
    float d = g_dinv[idx >> 5];
    int cb = (idx & 31) * 4;
    float4 a = ((const float4*)g_acc)[idx];
    float4 o;
    o.x = d * fmaxf(d * a.x + b1[cb],     0.f);
    o.y = d * fmaxf(d * a.y + b1[cb + 1], 0.f);
    o.z = d * fmaxf(d * a.z + b1[cb + 2], 0.f);
    o.w = d * fmaxf(d * a.w + b1[cb + 3], 0.f);
    ((float4*)g_hsd)[idx] = o;
}

// ================= output: [z_mu | z_logstd] = (dinv*acc) @ [Wmu|Wls] + bias ==
__global__ void k_out(const float* __restrict__ Wmu, const float* __restrict__ bmu,
                      const float* __restrict__ Wls, const float* __restrict__ bls,
                      float* __restrict__ out) {
    __shared__ float As[16][65];
    __shared__ float Bs[16 * 128];
    int row0 = blockIdx.x * 64;
    int tid = threadIdx.x;
    int tx = tid & 15, ty = tid >> 4;
    unsigned long long acc[4][4] = {};
    for (int k0 = 0; k0 < 128; k0 += 16) {
        for (int l = tid; l < 64 * 16; l += 256) {
            int i = l >> 4, kk = l & 15;
            As[kk][i] = g_acc[(row0 + i) * F + k0 + kk] * g_dinv[row0 + i];
        }
        for (int l = tid; l < 16 * 128; l += 256) {
            int kk = l >> 7, j = l & 127;
            Bs[kk * 128 + j] = (j < 64) ? Wmu[(k0 + kk) * LATD + j]
                                        : Wls[(k0 + kk) * LATD + (j - 64)];
        }
        __syncthreads();
#pragma unroll
        for (int kk = 0; kk < 16; kk++) {
            unsigned long long ad[4], bb[4];
#pragma unroll
            for (int m = 0; m < 4; m++) { float a = As[kk][ty + m * 16]; ad[m] = pk2(a, a); }
            const float2* brow = (const float2*)(Bs + kk * 128);
#pragma unroll
            for (int n = 0; n < 4; n++) { float2 bv = brow[tx + n * 16]; bb[n] = pk2(bv.x, bv.y); }
#pragma unroll
            for (int m = 0; m < 4; m++)
#pragma unroll
                for (int n = 0; n < 4; n++) fma2(acc[m][n], ad[m], bb[n]);
        }
        __syncthreads();
    }
#pragma unroll
    for (int m = 0; m < 4; m++) {
        int r = row0 + ty + m * 16;
#pragma unroll
        for (int n = 0; n < 4; n++) {
            float2 v = upk2(acc[m][n]);
            int j = 2 * (tx + n * 16);              // 0..126, pairs never cross 64
            if (j < 64) {
                out[r * LATD + j]     = v.x + bmu[j];
                out[r * LATD + j + 1] = v.y + bmu[j + 1];
            } else {
                int jj = j - 64;
                out[NN * LATD + r * LATD + jj]     = v.x + bls[jj];
                out[NN * LATD + r * LATD + jj + 1] = v.y + bls[jj + 1];
            }
        }
    }
}

// ================= launch ====================================================
extern "C" void kernel_launch(void* const* d_in, const int* in_sizes, int n_in,
                              void* d_out, int out_size) {
    const float* x   = (const float*)d_in[0];
    const float* my  = (const float*)d_in[1];
    const float* W1  = (const float*)d_in[2];
    const float* b1  = (const float*)d_in[3];
    const float* Wmu = (const float*)d_in[4];
    const float* bmu = (const float*)d_in[5];
    const float* Wls = (const float*)d_in[6];
    const float* bls = (const float*)d_in[7];
    const int*   ei  = (const int*)d_in[8];
    float* out = (float*)d_out;

    void *p_colsum, *p_cnt, *p_hsd;
    cudaGetSymbolAddress(&p_colsum, g_colsum);
    cudaGetSymbolAddress(&p_cnt,    g_cnt);
    cudaGetSymbolAddress(&p_hsd,    g_hsd);
    const float* hsd = (const float*)p_hsd;

    cudaMemsetAsync(p_colsum, 0, HALF * sizeof(float));
    cudaMemsetAsync(p_cnt,    0, NN * sizeof(int));

    k_megaA<<<1344, 256>>>(my, ei, x, W1);
    k_scan<<<1, 1024>>>();
    k_fill_scale<<<512, 256>>>(ei);

    // pass 1: edge (plain store) then dense (atomic add)
    k_agg_edge<<<NN, 128>>>(hsd);
    k_agg_dense<<<256, 256>>>(hsd);
    k_fin1<<<256, 256>>>(b1);

    // pass 2
    k_agg_edge<<<NN, 128>>>(hsd);
    k_agg_dense<<<256, 256>>>(hsd);

    k_out<<<32, 256>>>(Wmu, bmu, Wls, bls, out);
}